// round 1
// baseline (speedup 1.0000x reference)
#include <cuda_runtime.h>
#include <math.h>

#define Bb 2
#define Ss 2048
#define Dd 1024
#define Hh 16
#define DHh 64
#define DQK 128
#define BQ 64
#define BKT 64
#define QSTR 129
#define PSTR 65
#define INV_SCALE 0.08838834764831845f  // 1/sqrt(128)

// scratch (no cudaMalloc allowed)
__device__ float g_pos_kq[Ss * 2 * Dd];        // [S, 2D]
__device__ float g_tok[Bb * Ss * 3 * Dd];      // [B*S, 3D]
__device__ float g_bias_delta[Hh * 4096];      // [H, delta+2047]

// ---------------------------------------------------------------------------
// T5 relative-position bias, collapsed to a per-head function of delta = k - q
// ---------------------------------------------------------------------------
__global__ void bias_kernel(const float* __restrict__ bias_table) {
    int idx = blockIdx.x * blockDim.x + threadIdx.x;
    if (idx >= Hh * 4096) return;
    int h = idx >> 12;
    int dd = idx & 4095;
    int delta = dd - 2047;         // k - q
    int n = -delta;                // q - k
    int ret = 0;
    if (n < 0) { ret = 16; n = -n; }   // bidirectional: half-buckets = 16
    int bucket;
    if (n < 8) {
        bucket = n;
    } else {
        float v = logf((float)n / 8.0f) / logf(16.0f) * 8.0f;
        int vi = 8 + (int)v;
        bucket = vi < 15 ? vi : 15;
    }
    bucket += ret;
    g_bias_delta[idx] = bias_table[(bucket + 2048) * Hh + h];
}

// ---------------------------------------------------------------------------
// fp32 SGEMM: C[M,N] = A[M,K] @ B[K,N]; M,N % 128 == 0, K % 16 == 0
// 256 threads, 128x128 block tile, 8x8 per-thread microtile
// ---------------------------------------------------------------------------
__global__ void __launch_bounds__(256) sgemm_kernel(
    const float* __restrict__ A, const float* __restrict__ Bm,
    float* __restrict__ C, int M, int N, int K)
{
    __shared__ float As[16][128];   // transposed A tile
    __shared__ float Bs[16][128];
    const int tid = threadIdx.x;
    const int row0 = blockIdx.y * 128;
    const int col0 = blockIdx.x * 128;
    const int ty = tid >> 4, tx = tid & 15;
    float acc[8][8] = {};

    for (int k0 = 0; k0 < K; k0 += 16) {
#pragma unroll
        for (int t = 0; t < 2; t++) {
            int idx = tid + t * 256;
            int r = idx >> 2, c4 = (idx & 3) << 2;
            float4 av = *(const float4*)&A[(size_t)(row0 + r) * K + k0 + c4];
            As[c4 + 0][r] = av.x; As[c4 + 1][r] = av.y;
            As[c4 + 2][r] = av.z; As[c4 + 3][r] = av.w;
            int rb = idx >> 5, cb4 = (idx & 31) << 2;
            *(float4*)&Bs[rb][cb4] =
                *(const float4*)&Bm[(size_t)(k0 + rb) * N + col0 + cb4];
        }
        __syncthreads();
#pragma unroll
        for (int kk = 0; kk < 16; kk++) {
            float a[8], b[8];
            *(float4*)&a[0] = *(const float4*)&As[kk][ty * 8];
            *(float4*)&a[4] = *(const float4*)&As[kk][ty * 8 + 4];
            *(float4*)&b[0] = *(const float4*)&Bs[kk][tx * 8];
            *(float4*)&b[4] = *(const float4*)&Bs[kk][tx * 8 + 4];
#pragma unroll
            for (int i = 0; i < 8; i++)
#pragma unroll
                for (int j = 0; j < 8; j++)
                    acc[i][j] += a[i] * b[j];
        }
        __syncthreads();
    }
#pragma unroll
    for (int i = 0; i < 8; i++) {
        float* cp = &C[(size_t)(row0 + ty * 8 + i) * N + col0 + tx * 8];
        *(float4*)cp       = make_float4(acc[i][0], acc[i][1], acc[i][2], acc[i][3]);
        *(float4*)(cp + 4) = make_float4(acc[i][4], acc[i][5], acc[i][6], acc[i][7]);
    }
}

// ---------------------------------------------------------------------------
// Flash attention: combined 128-dim QK (tok||pos), 64-dim V, online softmax.
// One block per (q-tile 64, head, batch). 256 threads = 16x16 grid, 4x4 tiles.
// ---------------------------------------------------------------------------
constexpr int SM_K = BQ * QSTR;
constexpr int SM_V = SM_K + BKT * QSTR;
constexpr int SM_P = SM_V + BKT * DHh;
constexpr int SMEM_FLOATS = SM_P + BKT * PSTR;
constexpr int SMEM_BYTES = SMEM_FLOATS * 4;

__global__ void __launch_bounds__(256) attn_kernel(
    const float* __restrict__ tok, const float* __restrict__ pos,
    const float* __restrict__ biasd, float* __restrict__ out)
{
    extern __shared__ float sm[];
    float* Qs = sm;           // [BQ][QSTR]
    float* Ks = sm + SM_K;    // [BKT][QSTR]
    float* Vs = sm + SM_V;    // [BKT][64]
    float* Ps = sm + SM_P;    // [BKT][PSTR] transposed P

    const int b = blockIdx.z, h = blockIdx.y;
    const int q0 = blockIdx.x * BQ;
    const int tid = threadIdx.x;
    const int ty = tid >> 4, tx = tid & 15;
    const float* bd = biasd + h * 4096;

    // Load Q tile: dims 0..63 = tok_query, 64..127 = pos_query
#pragma unroll
    for (int t = 0; t < 8; t++) {
        int idx = tid + t * 256;
        int r = idx >> 5, part = idx & 31;
        const float* src = (part < 16)
            ? &tok[(size_t)(b * Ss + q0 + r) * 3072 + 1024 + h * 64 + part * 4]
            : &pos[(size_t)(q0 + r) * 2048 + 1024 + h * 64 + (part - 16) * 4];
        float4 v = *(const float4*)src;
        float* dst = &Qs[r * QSTR + part * 4];
        dst[0] = v.x; dst[1] = v.y; dst[2] = v.z; dst[3] = v.w;
    }

    float m_i[4], l_i[4] = {0.f, 0.f, 0.f, 0.f};
    float o[4][4] = {};
    m_i[0] = m_i[1] = m_i[2] = m_i[3] = -INFINITY;

    for (int k0 = 0; k0 < Ss; k0 += BKT) {
        __syncthreads();
        // Load K tile (tok_key || pos_key)
#pragma unroll
        for (int t = 0; t < 8; t++) {
            int idx = tid + t * 256;
            int r = idx >> 5, part = idx & 31;
            const float* src = (part < 16)
                ? &tok[(size_t)(b * Ss + k0 + r) * 3072 + h * 64 + part * 4]
                : &pos[(size_t)(k0 + r) * 2048 + h * 64 + (part - 16) * 4];
            float4 v = *(const float4*)src;
            float* dst = &Ks[r * QSTR + part * 4];
            dst[0] = v.x; dst[1] = v.y; dst[2] = v.z; dst[3] = v.w;
        }
        // Load V tile
#pragma unroll
        for (int t = 0; t < 4; t++) {
            int idx = tid + t * 256;
            int r = idx >> 4, part = idx & 15;
            *(float4*)&Vs[r * 64 + part * 4] =
                *(const float4*)&tok[(size_t)(b * Ss + k0 + r) * 3072 + 2048 + h * 64 + part * 4];
        }
        __syncthreads();

        // S = Qc Kc^T over 128 dims
        float s[4][4] = {};
#pragma unroll 4
        for (int d = 0; d < DQK; d++) {
            float qr[4], kr[4];
#pragma unroll
            for (int i = 0; i < 4; i++) qr[i] = Qs[(ty * 4 + i) * QSTR + d];
#pragma unroll
            for (int j = 0; j < 4; j++) kr[j] = Ks[(tx * 4 + j) * QSTR + d];
#pragma unroll
            for (int i = 0; i < 4; i++)
#pragma unroll
                for (int j = 0; j < 4; j++)
                    s[i][j] += qr[i] * kr[j];
        }

        // scale + relative-position bias
        const int dbase = (k0 - q0) + 2047 + tx * 4 - ty * 4;
#pragma unroll
        for (int i = 0; i < 4; i++)
#pragma unroll
            for (int j = 0; j < 4; j++)
                s[i][j] = s[i][j] * INV_SCALE + bd[dbase + j - i];

        // online softmax (row reduce over 16 lanes of tx)
#pragma unroll
        for (int i = 0; i < 4; i++) {
            float mt = fmaxf(fmaxf(s[i][0], s[i][1]), fmaxf(s[i][2], s[i][3]));
#pragma unroll
            for (int off = 8; off; off >>= 1)
                mt = fmaxf(mt, __shfl_xor_sync(0xffffffffu, mt, off));
            float mnew = fmaxf(m_i[i], mt);
            float corr = expf(m_i[i] - mnew);
            float rs = 0.f;
#pragma unroll
            for (int j = 0; j < 4; j++) {
                float p = expf(s[i][j] - mnew);
                s[i][j] = p;
                rs += p;
            }
#pragma unroll
            for (int off = 8; off; off >>= 1)
                rs += __shfl_xor_sync(0xffffffffu, rs, off);
            l_i[i] = l_i[i] * corr + rs;
            m_i[i] = mnew;
#pragma unroll
            for (int j = 0; j < 4; j++) o[i][j] *= corr;
#pragma unroll
            for (int j = 0; j < 4; j++)
                Ps[(tx * 4 + j) * PSTR + ty * 4 + i] = s[i][j];
        }
        __syncthreads();

        // O += P @ V
#pragma unroll 2
        for (int kk = 0; kk < BKT; kk++) {
            float4 v = *(const float4*)&Vs[kk * 64 + tx * 4];
#pragma unroll
            for (int i = 0; i < 4; i++) {
                float p = Ps[kk * PSTR + ty * 4 + i];
                o[i][0] += p * v.x; o[i][1] += p * v.y;
                o[i][2] += p * v.z; o[i][3] += p * v.w;
            }
        }
    }

    // normalize + store: out[b, q, h*64 + dh]
#pragma unroll
    for (int i = 0; i < 4; i++) {
        float inv = 1.0f / l_i[i];
        float4 r = make_float4(o[i][0] * inv, o[i][1] * inv, o[i][2] * inv, o[i][3] * inv);
        *(float4*)&out[(size_t)(b * Ss + q0 + ty * 4 + i) * 1024 + h * 64 + tx * 4] = r;
    }
}

// ---------------------------------------------------------------------------
extern "C" void kernel_launch(void* const* d_in, const int* in_sizes, int n_in,
                              void* d_out, int out_size)
{
    const float* x          = (const float*)d_in[0];
    const float* pos_embed  = (const float*)d_in[1];
    const float* W_pos_kq   = (const float*)d_in[2];
    const float* W_tok_kqv  = (const float*)d_in[3];
    const float* bias_table = (const float*)d_in[4];
    float* out = (float*)d_out;

    float *pos_kq, *tok, *biasd;
    cudaGetSymbolAddress((void**)&pos_kq, g_pos_kq);
    cudaGetSymbolAddress((void**)&tok, g_tok);
    cudaGetSymbolAddress((void**)&biasd, g_bias_delta);

    cudaFuncSetAttribute(attn_kernel,
                         cudaFuncAttributeMaxDynamicSharedMemorySize, SMEM_BYTES);

    bias_kernel<<<(Hh * 4096) / 256, 256>>>(bias_table);
    // pos_kq = pos_embed[2048,1024] @ W_pos_kq[1024,2048]
    sgemm_kernel<<<dim3(2048 / 128, 2048 / 128), 256>>>(pos_embed, W_pos_kq, pos_kq,
                                                        2048, 2048, 1024);
    // tok = x[4096,1024] @ W_tok_kqv[1024,3072]
    sgemm_kernel<<<dim3(3072 / 128, 4096 / 128), 256>>>(x, W_tok_kqv, tok,
                                                        4096, 3072, 1024);
    attn_kernel<<<dim3(Ss / BQ, Hh, Bb), 256, SMEM_BYTES>>>(tok, pos_kq, biasd, out);
}